// round 6
// baseline (speedup 1.0000x reference)
#include <cuda_runtime.h>
#include <cuda_bf16.h>
#include <math.h>
#include <stdint.h>

#define Bdim 4096
#define DIN  512
#define Hdim 512
#define Edim 256
#define Vdim 512
#define Ldim 32
#define MIN_REAL (-3.4028234663852886e38f)

// ---------------- scratch (device globals; no allocation allowed) ----------
__device__ float         g_h[2][(size_t)Bdim * Hdim];      // fp32 hidden (master)
__device__ __nv_bfloat16 g_abf[2][(size_t)Bdim * 768];     // [e | h] bf16, ping-pong
__device__ float         g_logits[(size_t)Bdim * Vdim];
__device__ __nv_bfloat16 g_sbf[(size_t)Bdim * Vdim];       // bf16 sample
__device__ __nv_bfloat16 g_xbf[(size_t)Bdim * DIN];
__device__ __nv_bfloat16 g_wbig[2048 * 768];               // gate-interleaved GRU weights
__device__ float         g_bbig[2048];                     // interleaved biases
__device__ __nv_bfloat16 g_wo[512 * 512];
__device__ __nv_bfloat16 g_we[256 * 512];
__device__ __nv_bfloat16 g_wa[512 * 512];

__device__ __forceinline__ float sigm(float x) { return 1.f / (1.f + expf(-x)); }

#define MMA_BF16(d, a, b) \
    asm volatile("mma.sync.aligned.m16n8k16.row.col.f32.bf16.bf16.f32 " \
        "{%0,%1,%2,%3}, {%4,%5,%6,%7}, {%8,%9}, {%0,%1,%2,%3};" \
        : "+f"((d)[0]), "+f"((d)[1]), "+f"((d)[2]), "+f"((d)[3]) \
        : "r"((a)[0]), "r"((a)[1]), "r"((a)[2]), "r"((a)[3]), \
          "r"((b)[0]), "r"((b)[1]))

#define LDM_X4(d, addr) \
    asm volatile("ldmatrix.sync.aligned.m8n8.x4.shared.b16 {%0,%1,%2,%3}, [%4];" \
        : "=r"((d)[0]), "=r"((d)[1]), "=r"((d)[2]), "=r"((d)[3]) : "r"(addr))

__device__ __forceinline__ void cp16(uint32_t dst, const void* src) {
    asm volatile("cp.async.cg.shared.global [%0], [%1], 16;" :: "r"(dst), "l"(src) : "memory");
}
#define CP_COMMIT  asm volatile("cp.async.commit_group;" ::: "memory")
#define CP_WAIT2   asm volatile("cp.async.wait_group 2;" ::: "memory")

// ---------------- prep kernels ----------------------------------------------
__global__ void cvt_kernel(__nv_bfloat16* __restrict__ dst,
                           const float* __restrict__ src, int n) {
    int i = blockIdx.x * blockDim.x + threadIdx.x;
    if (i < n) dst[i] = __float2bfloat16_rn(src[i]);
}
// W_big row 4j+g over K=768 ([e|h]):
//  g=0: [Wih_r(j) | Whh_r(j)]   g=1: [Wih_z(j) | Whh_z(j)]
//  g=2: [Wih_n(j) | 0]          g=3: [0 | Whh_n(j)]
__global__ void build_wbig_kernel(const float* __restrict__ Wih,
                                  const float* __restrict__ Whh) {
    int i = blockIdx.x * blockDim.x + threadIdx.x;   // 2048*768
    int row = i / 768, col = i % 768;
    int j = row >> 2, g = row & 3;
    float v = 0.f;
    if (g == 0) v = (col < 256) ? Wih[j * 256 + col] : Whh[j * 512 + col - 256];
    else if (g == 1) v = (col < 256) ? Wih[(512 + j) * 256 + col]
                                     : Whh[(512 + j) * 512 + col - 256];
    else if (g == 2) { if (col < 256) v = Wih[(1024 + j) * 256 + col]; }
    else             { if (col >= 256) v = Whh[(1024 + j) * 512 + col - 256]; }
    g_wbig[i] = __float2bfloat16_rn(v);
}
__global__ void build_bbig_kernel(const float* __restrict__ bih,
                                  const float* __restrict__ bhh) {
    int i = blockIdx.x * blockDim.x + threadIdx.x;   // 2048
    int j = i >> 2, g = i & 3;
    float v;
    if (g == 0) v = bih[j] + bhh[j];
    else if (g == 1) v = bih[512 + j] + bhh[512 + j];
    else if (g == 2) v = bih[1024 + j];
    else v = bhh[1024 + j];
    g_bbig[i] = v;
}
__global__ void init_e0_kernel(const float* __restrict__ sos) {
    int i = blockIdx.x * blockDim.x + threadIdx.x;   // B*256
    int b = i >> 8, c = i & 255;
    g_abf[0][(size_t)b * 768 + c] = __float2bfloat16_rn(sos[c]);
}

// =================== shared GEMM mainloop machinery =========================
// Block 128x128, 256 thr, K-block 32; 4-stage cp.async; ldmatrix.x4 frags.
#define GEMM_PROLOGUE(Aptr, lda, Wptr, ldw)                                     \
    __shared__ __align__(1024) char smem[4 * 16384];                            \
    const int tid = threadIdx.x, wid = tid >> 5, lane = tid & 31;               \
    const int wm = wid & 3, wn = wid >> 2;                                      \
    const int m0 = blockIdx.y << 7, n0 = blockIdx.x << 7;                       \
    const uint32_t smbase = (uint32_t)__cvta_generic_to_shared(smem);           \
    float acc[2][8][4];                                                         \
    _Pragma("unroll") for (int a_ = 0; a_ < 2; a_++)                            \
    _Pragma("unroll") for (int b_ = 0; b_ < 8; b_++)                            \
    _Pragma("unroll") for (int c_ = 0; c_ < 4; c_++) acc[a_][b_][c_] = 0.f;     \
    const int cr = tid >> 2, cc = tid & 3;                                      \
    auto issue = [&](int kb, int s) {                                           \
        uint32_t sb = smbase + ((uint32_t)s << 14);                             \
        _Pragma("unroll") for (int it = 0; it < 2; ++it) {                      \
            int rr = cr + (it << 6);                                            \
            uint32_t off = (uint32_t)(((rr << 2) + (cc ^ ((rr >> 1) & 3))) << 4); \
            cp16(sb + off,        Aptr + (size_t)(m0 + rr) * lda + (kb << 5) + (cc << 3)); \
            cp16(sb + 8192 + off, Wptr + (size_t)(n0 + rr) * ldw + (kb << 5) + (cc << 3)); \
        }                                                                       \
    };                                                                          \
    const int arow0 = (wm << 5) + (lane & 7) + (((lane >> 3) & 1) << 3);        \
    const int acb = (lane >> 4) & 1;                                            \
    const int nrow0 = (wn << 6) + (lane & 7) + (((lane >> 4) & 1) << 3);        \
    const int bcb = (lane >> 3) & 1;                                            \
    auto compute = [&](int s) {                                                 \
        uint32_t ab = smbase + ((uint32_t)s << 14);                             \
        uint32_t bb = ab + 8192;                                                \
        _Pragma("unroll") for (int ks = 0; ks < 2; ++ks) {                      \
            uint32_t afr[2][4];                                                 \
            _Pragma("unroll") for (int mt = 0; mt < 2; ++mt) {                  \
                int row = arow0 + (mt << 4);                                    \
                int ch = (ks << 1) + acb;                                       \
                uint32_t addr = ab + (uint32_t)(((row << 2) + (ch ^ ((row >> 1) & 3))) << 4); \
                LDM_X4(afr[mt], addr);                                          \
            }                                                                   \
            uint32_t bfr[8][2];                                                 \
            _Pragma("unroll") for (int p = 0; p < 4; ++p) {                     \
                int row = nrow0 + (p << 4);                                     \
                int ch = (ks << 1) + bcb;                                       \
                uint32_t addr = bb + (uint32_t)(((row << 2) + (ch ^ ((row >> 1) & 3))) << 4); \
                uint32_t t[4];                                                  \
                LDM_X4(t, addr);                                                \
                bfr[2 * p][0] = t[0]; bfr[2 * p][1] = t[1];                     \
                bfr[2 * p + 1][0] = t[2]; bfr[2 * p + 1][1] = t[3];             \
            }                                                                   \
            _Pragma("unroll") for (int nt = 0; nt < 8; ++nt) {                  \
                MMA_BF16(acc[0][nt], afr[0], bfr[nt]);                          \
                MMA_BF16(acc[1][nt], afr[1], bfr[nt]);                          \
            }                                                                   \
        }                                                                       \
    };                                                                          \
    issue(0, 0); CP_COMMIT;                                                     \
    issue(1, 1); CP_COMMIT;                                                     \
    issue(2, 2); CP_COMMIT;                                                     \
    _Pragma("unroll 1") for (int kb = 0; kb < KB; ++kb) {                       \
        CP_WAIT2;                                                               \
        __syncthreads();                                                        \
        if (kb + 3 < KB) issue(kb + 3, (kb + 3) & 3);                           \
        CP_COMMIT;                                                              \
        compute(kb & 3);                                                        \
    }

// ======================= generic bf16 GEMM ==================================
__global__ __launch_bounds__(256, 2) void gemm_bf(
    const __nv_bfloat16* __restrict__ A, int lda,
    const __nv_bfloat16* __restrict__ W, int K,
    const float* __restrict__ bias,
    float* __restrict__ C, int ldc,
    __nv_bfloat16* __restrict__ Cbf, int ldcb)
{
    const int KB = K >> 5;
    GEMM_PROLOGUE(A, lda, W, K)
#pragma unroll
    for (int mt = 0; mt < 2; ++mt) {
#pragma unroll
        for (int nt = 0; nt < 8; ++nt) {
            int row = m0 + (wm << 5) + (mt << 4) + (lane >> 2);
            int col = n0 + (wn << 6) + (nt << 3) + ((lane & 3) << 1);
            float2 bv = *(const float2*)&bias[col];
            float2 o0 = {acc[mt][nt][0] + bv.x, acc[mt][nt][1] + bv.y};
            float2 o1 = {acc[mt][nt][2] + bv.x, acc[mt][nt][3] + bv.y};
            if (C) {
                *(float2*)&C[(size_t)row * ldc + col] = o0;
                *(float2*)&C[(size_t)(row + 8) * ldc + col] = o1;
            }
            if (Cbf) {
                __nv_bfloat162 p0 = {__float2bfloat16_rn(o0.x), __float2bfloat16_rn(o0.y)};
                __nv_bfloat162 p1 = {__float2bfloat16_rn(o1.x), __float2bfloat16_rn(o1.y)};
                *(__nv_bfloat162*)&Cbf[(size_t)row * ldcb + col] = p0;
                *(__nv_bfloat162*)&Cbf[(size_t)(row + 8) * ldcb + col] = p1;
            }
        }
    }
}

// ======================= fused GRU GEMM =====================================
// A'[B,768] @ W_big[2048,768]^T; cols gate-interleaved (4j+g). Epilogue does
// full GRU cell update and writes h fp32 + bf16.
__global__ __launch_bounds__(256, 2) void gemm_gru(
    const __nv_bfloat16* __restrict__ A,
    const __nv_bfloat16* __restrict__ W,
    const float* __restrict__ bias,
    const float* __restrict__ hin,
    float* __restrict__ hout,
    __nv_bfloat16* __restrict__ habf)
{
    const int KB = 24;   // K = 768
    GEMM_PROLOGUE(A, 768, W, 768)

    __syncthreads();     // done with pipeline smem; reuse for staging
    float* sh_hin  = (float*)smem;             // [128][33]
    float* sh_hnew = (float*)(smem + 17408);   // [128][33]
    const int j0g = n0 >> 2;                   // 32 h-cols per block

    // coalesced hin tile load
#pragma unroll
    for (int k = 0; k < 16; ++k) {
        int idx = tid + (k << 8);
        int r = idx >> 5, j = idx & 31;
        sh_hin[r * 33 + j] = hin[(size_t)(m0 + r) * Hdim + j0g + j];
    }
    __syncthreads();

    // gate combine + GRU update (lane pair exchange via shfl_xor 1)
#pragma unroll
    for (int mt = 0; mt < 2; ++mt) {
#pragma unroll
        for (int nt = 0; nt < 8; ++nt) {
            int colb = (wn << 6) + (nt << 3) + ((lane & 3) << 1);
            float2 bv = *(const float2*)&bias[n0 + colb];
            float a0 = acc[mt][nt][0] + bv.x, a1 = acc[mt][nt][1] + bv.y;
            float a2 = acc[mt][nt][2] + bv.x, a3 = acc[mt][nt][3] + bv.y;
            float o0 = __shfl_xor_sync(0xffffffffu, a0, 1);
            float o1 = __shfl_xor_sync(0xffffffffu, a1, 1);
            float o2 = __shfl_xor_sync(0xffffffffu, a2, 1);
            float o3 = __shfl_xor_sync(0xffffffffu, a3, 1);
            int jl = (wn << 4) + (nt << 1) + ((lane >> 1) & 1);
            int rl = (wm << 5) + (mt << 4) + (lane >> 2) + ((lane & 1) << 3);
            float rg, zg, ig, hg;
            if ((lane & 1) == 0) { rg = a0; zg = a1; ig = o0; hg = o1; }
            else                 { rg = o2; zg = o3; ig = a2; hg = a3; }
            float rs = sigm(rg), zs = sigm(zg);
            float hold = sh_hin[rl * 33 + jl];
            sh_hnew[rl * 33 + jl] = (1.f - zs) * tanhf(ig + rs * hg) + zs * hold;
        }
    }
    __syncthreads();

    // coalesced writeout: fp32 h + bf16 h
#pragma unroll
    for (int k = 0; k < 16; ++k) {
        int idx = tid + (k << 8);
        int r = idx >> 5, j = idx & 31;
        float v = sh_hnew[r * 33 + j];
        hout[(size_t)(m0 + r) * Hdim + j0g + j] = v;
        habf[(size_t)(m0 + r) * 768 + 256 + j0g + j] = __float2bfloat16_rn(v);
    }
}

// ======================= gumbel softmax + entropy ===========================
__global__ __launch_bounds__(256) void softmax_kernel(
    const float* __restrict__ logits, const float* __restrict__ u,
    float* __restrict__ seq, float* __restrict__ ent,
    __nv_bfloat16* __restrict__ sbf, int l)
{
    const int warp = threadIdx.x >> 5, lane = threadIdx.x & 31;
    const int b = blockIdx.x * 8 + warp;
    const float* lrow = logits + (size_t)b * Vdim;
    const float* urow = u + (size_t)b * Vdim;

    float s[16];
    float m = -INFINITY;
#pragma unroll
    for (int i = 0; i < 16; i++) {
        float uu = urow[lane + 32 * i];
        float g = -logf(-logf(uu));
        s[i] = lrow[lane + 32 * i] + g;
        m = fmaxf(m, s[i]);
    }
#pragma unroll
    for (int o = 16; o; o >>= 1) m = fmaxf(m, __shfl_xor_sync(0xffffffffu, m, o));
    float sum = 0.f;
#pragma unroll
    for (int i = 0; i < 16; i++) { s[i] = expf(s[i] - m); sum += s[i]; }
#pragma unroll
    for (int o = 16; o; o >>= 1) sum += __shfl_xor_sync(0xffffffffu, sum, o);

    float inv = 1.f / sum;
    float eacc = 0.f;
    float* srow = seq + ((size_t)b * Ldim + l) * Vdim;
    __nv_bfloat16* brow = sbf + (size_t)b * Vdim;
#pragma unroll
    for (int i = 0; i < 16; i++) {
        float p = s[i] * inv;
        srow[lane + 32 * i] = p;
        brow[lane + 32 * i] = __float2bfloat16_rn(p);
        float t = fmaxf(log2f(p), MIN_REAL);
        eacc -= p * t;
    }
#pragma unroll
    for (int o = 16; o; o >>= 1) eacc += __shfl_xor_sync(0xffffffffu, eacc, o);
    if (lane == 0) ent[(size_t)b * Ldim + l] = eacc;
}

// ======================= host launcher ======================================
extern "C" void kernel_launch(void* const* d_in, const int* in_sizes, int n_in,
                              void* d_out, int out_size)
{
    const float* x       = (const float*)d_in[0];
    const float* noise   = (const float*)d_in[1];
    const float* W_agent = (const float*)d_in[2];
    const float* b_agent = (const float*)d_in[3];
    const float* W_ih    = (const float*)d_in[4];
    const float* W_hh    = (const float*)d_in[5];
    const float* b_ih    = (const float*)d_in[6];
    const float* b_hh    = (const float*)d_in[7];
    const float* W_out   = (const float*)d_in[8];
    const float* b_out   = (const float*)d_in[9];
    const float* W_emb   = (const float*)d_in[10];
    const float* b_emb   = (const float*)d_in[11];
    const float* sos     = (const float*)d_in[12];

    float* out = (float*)d_out;
    float* ent = out + (size_t)Bdim * Ldim * Vdim;

    float *hbuf0, *lbuf, *bbig;
    __nv_bfloat16 *abf0, *sbf, *xbf, *wbig, *wo, *we, *wa;
    cudaGetSymbolAddress((void**)&hbuf0, g_h);
    float* hbuf1 = hbuf0 + (size_t)Bdim * Hdim;
    cudaGetSymbolAddress((void**)&abf0, g_abf);
    __nv_bfloat16* abf1 = abf0 + (size_t)Bdim * 768;
    cudaGetSymbolAddress((void**)&lbuf, g_logits);
    cudaGetSymbolAddress((void**)&sbf, g_sbf);
    cudaGetSymbolAddress((void**)&xbf, g_xbf);
    cudaGetSymbolAddress((void**)&wbig, g_wbig);
    cudaGetSymbolAddress((void**)&bbig, g_bbig);
    cudaGetSymbolAddress((void**)&wo, g_wo);
    cudaGetSymbolAddress((void**)&we, g_we);
    cudaGetSymbolAddress((void**)&wa, g_wa);

    // ---- one-time prep ----
    build_wbig_kernel<<<(2048 * 768) / 256, 256>>>(W_ih, W_hh);
    build_bbig_kernel<<<8, 256>>>(b_ih, b_hh);
    cvt_kernel<<<(512 * 512) / 256, 256>>>(wo, W_out, 512 * 512);
    cvt_kernel<<<(256 * 512) / 256, 256>>>(we, W_emb, 256 * 512);
    cvt_kernel<<<(512 * 512) / 256, 256>>>(wa, W_agent, 512 * 512);
    cvt_kernel<<<(Bdim * DIN) / 256, 256>>>(xbf, x, Bdim * DIN);
    init_e0_kernel<<<(Bdim * Edim) / 256, 256>>>(sos);

    // h0 = x @ W_agent^T + b_agent  (fp32 master + bf16 into A'[0] h-slot)
    gemm_bf<<<dim3(4, 32), 256>>>(xbf, DIN, wa, DIN, b_agent,
                                  hbuf0, Hdim, abf0 + 256, 768);

    for (int l = 0; l < Ldim; l++) {
        __nv_bfloat16* Ain  = (l & 1) ? abf1 : abf0;
        __nv_bfloat16* Anxt = (l & 1) ? abf0 : abf1;
        float* hin  = (l & 1) ? hbuf1 : hbuf0;
        float* hout = (l & 1) ? hbuf0 : hbuf1;

        // fused: all gates + GRU update -> hout fp32, bf16 h into A'[next]
        gemm_gru<<<dim3(16, 32), 256>>>(Ain, wbig, bbig, hin, hout, Anxt);
        // logits = h_t @ W_out^T + b_out
        gemm_bf<<<dim3(4, 32), 256>>>(Anxt + 256, 768, wo, 512, b_out,
                                      lbuf, 512, (__nv_bfloat16*)0, 0);
        // sample + entropy (+ bf16 sample)
        softmax_kernel<<<Bdim / 8, 256>>>(
            lbuf, noise + (size_t)l * Bdim * Vdim, out, ent, sbf, l);
        // e_{l+1} = sample @ W_emb^T + b_emb -> bf16 into A'[next] e-slot
        gemm_bf<<<dim3(2, 32), 256>>>(sbf, 512, we, 512, b_emb,
                                      (float*)0, 0, Anxt, 768);
    }
    (void)in_sizes; (void)n_in; (void)out_size;
}

// round 7
// speedup vs baseline: 1.0310x; 1.0310x over previous
#include <cuda_runtime.h>
#include <cuda_bf16.h>
#include <math.h>
#include <stdint.h>

#define Bdim 4096
#define DIN  512
#define Hdim 512
#define Edim 256
#define Vdim 512
#define Ldim 32
#define MIN_REAL (-3.4028234663852886e38f)

// ---------------- scratch (device globals; no allocation allowed) ----------
__device__ float         g_h[2][(size_t)Bdim * Hdim];      // fp32 hidden (master)
__device__ __nv_bfloat16 g_abf[2][(size_t)Bdim * 768];     // [e | h] bf16, ping-pong
__device__ float         g_grz[(size_t)Bdim * 1024];       // summed r,z pre-activations
__device__ float         g_in[(size_t)Bdim * Hdim];        // i_n (+b_ih_n)
__device__ __nv_bfloat16 g_xbf[(size_t)Bdim * DIN];
__device__ __nv_bfloat16 g_wrz[1024 * 768];                // [Wih_rz | Whh_rz]
__device__ __nv_bfloat16 g_wihn[512 * 256];
__device__ __nv_bfloat16 g_whhn[512 * 512];
__device__ __nv_bfloat16 g_wo[512 * 512];
__device__ __nv_bfloat16 g_we[256 * 512];
__device__ __nv_bfloat16 g_wa[512 * 512];
__device__ float         g_brz[1024];

__device__ __forceinline__ float sigm(float x) { return 1.f / (1.f + expf(-x)); }

#define MMA_BF16(d, a, b) \
    asm volatile("mma.sync.aligned.m16n8k16.row.col.f32.bf16.bf16.f32 " \
        "{%0,%1,%2,%3}, {%4,%5,%6,%7}, {%8,%9}, {%0,%1,%2,%3};" \
        : "+f"((d)[0]), "+f"((d)[1]), "+f"((d)[2]), "+f"((d)[3]) \
        : "r"((a)[0]), "r"((a)[1]), "r"((a)[2]), "r"((a)[3]), \
          "r"((b)[0]), "r"((b)[1]))

#define LDM_X4(d, addr) \
    asm volatile("ldmatrix.sync.aligned.m8n8.x4.shared.b16 {%0,%1,%2,%3}, [%4];" \
        : "=r"((d)[0]), "=r"((d)[1]), "=r"((d)[2]), "=r"((d)[3]) : "r"(addr))

__device__ __forceinline__ void cp16(uint32_t dst, const void* src) {
    asm volatile("cp.async.cg.shared.global [%0], [%1], 16;" :: "r"(dst), "l"(src) : "memory");
}
#define CP_COMMIT  asm volatile("cp.async.commit_group;" ::: "memory")
#define CP_WAIT2   asm volatile("cp.async.wait_group 2;" ::: "memory")
#define CP_WAIT0   asm volatile("cp.async.wait_group 0;" ::: "memory")

// swizzled byte offset for (row, 8-elem chunk) in a 32-col bf16 k-slab tile
#define SWZ(r, c) ((uint32_t)((((r) << 2) + ((c) ^ (((r) >> 1) & 3))) << 4))

// ---------------- prep kernels ----------------------------------------------
__global__ void cvt_kernel(__nv_bfloat16* __restrict__ dst,
                           const float* __restrict__ src, int n) {
    int i = blockIdx.x * blockDim.x + threadIdx.x;
    if (i < n) dst[i] = __float2bfloat16_rn(src[i]);
}
__global__ void build_wrz_kernel(const float* __restrict__ Wih,
                                 const float* __restrict__ Whh) {
    int i = blockIdx.x * blockDim.x + threadIdx.x;   // 1024*768
    int g = i / 768, c = i % 768;
    float v = (c < 256) ? Wih[g * 256 + c] : Whh[g * 512 + (c - 256)];
    g_wrz[i] = __float2bfloat16_rn(v);
}
__global__ void build_brz_kernel(const float* __restrict__ bih,
                                 const float* __restrict__ bhh) {
    int i = blockIdx.x * blockDim.x + threadIdx.x;   // 1024
    g_brz[i] = bih[i] + bhh[i];
}
__global__ void init_e0_kernel(const float* __restrict__ sos) {
    int i = blockIdx.x * blockDim.x + threadIdx.x;   // B*256
    int b = i >> 8, c = i & 255;
    g_abf[0][(size_t)b * 768 + c] = __float2bfloat16_rn(sos[c]);
}

// =================== shared GEMM mainloop machinery =========================
// Block 128x128, 256 thr, K-block 32; 4-stage cp.async; ldmatrix.x4 frags.
#define GEMM_PROLOGUE(Aptr, lda, Wptr, ldw)                                     \
    __shared__ __align__(1024) char smem[4 * 16384];                            \
    const int tid = threadIdx.x, wid = tid >> 5, lane = tid & 31;               \
    const int wm = wid & 3, wn = wid >> 2;                                      \
    const int m0 = blockIdx.y << 7, n0 = blockIdx.x << 7;                       \
    const uint32_t smbase = (uint32_t)__cvta_generic_to_shared(smem);           \
    float acc[2][8][4];                                                         \
    _Pragma("unroll") for (int a_ = 0; a_ < 2; a_++)                            \
    _Pragma("unroll") for (int b_ = 0; b_ < 8; b_++)                            \
    _Pragma("unroll") for (int c_ = 0; c_ < 4; c_++) acc[a_][b_][c_] = 0.f;     \
    const int cr = tid >> 2, cc = tid & 3;                                      \
    auto issue = [&](int kb, int s) {                                           \
        uint32_t sb = smbase + ((uint32_t)s << 14);                             \
        _Pragma("unroll") for (int it = 0; it < 2; ++it) {                      \
            int rr = cr + (it << 6);                                            \
            uint32_t off = SWZ(rr, cc);                                         \
            cp16(sb + off,        Aptr + (size_t)(m0 + rr) * lda + (kb << 5) + (cc << 3)); \
            cp16(sb + 8192 + off, Wptr + (size_t)(n0 + rr) * ldw + (kb << 5) + (cc << 3)); \
        }                                                                       \
    };                                                                          \
    const int arow0 = (wm << 5) + (lane & 7) + (((lane >> 3) & 1) << 3);        \
    const int acb = (lane >> 4) & 1;                                            \
    const int nrow0 = (wn << 6) + (lane & 7) + (((lane >> 4) & 1) << 3);        \
    const int bcb = (lane >> 3) & 1;                                            \
    auto compute = [&](int s) {                                                 \
        uint32_t ab = smbase + ((uint32_t)s << 14);                             \
        uint32_t bb = ab + 8192;                                                \
        _Pragma("unroll") for (int ks = 0; ks < 2; ++ks) {                      \
            uint32_t afr[2][4];                                                 \
            _Pragma("unroll") for (int mt = 0; mt < 2; ++mt) {                  \
                int row = arow0 + (mt << 4);                                    \
                int ch = (ks << 1) + acb;                                       \
                LDM_X4(afr[mt], ab + SWZ(row, ch));                             \
            }                                                                   \
            uint32_t bfr[8][2];                                                 \
            _Pragma("unroll") for (int p = 0; p < 4; ++p) {                     \
                int row = nrow0 + (p << 4);                                     \
                int ch = (ks << 1) + bcb;                                       \
                uint32_t t[4];                                                  \
                LDM_X4(t, bb + SWZ(row, ch));                                   \
                bfr[2 * p][0] = t[0]; bfr[2 * p][1] = t[1];                     \
                bfr[2 * p + 1][0] = t[2]; bfr[2 * p + 1][1] = t[3];             \
            }                                                                   \
            _Pragma("unroll") for (int nt = 0; nt < 8; ++nt) {                  \
                MMA_BF16(acc[0][nt], afr[0], bfr[nt]);                          \
                MMA_BF16(acc[1][nt], afr[1], bfr[nt]);                          \
            }                                                                   \
        }                                                                       \
    };                                                                          \
    issue(0, 0); CP_COMMIT;                                                     \
    issue(1, 1); CP_COMMIT;                                                     \
    issue(2, 2); CP_COMMIT;                                                     \
    _Pragma("unroll 1") for (int kb = 0; kb < KB; ++kb) {                       \
        CP_WAIT2;                                                               \
        __syncthreads();                                                        \
        if (kb + 3 < KB) issue(kb + 3, (kb + 3) & 3);                           \
        CP_COMMIT;                                                              \
        compute(kb & 3);                                                        \
    }

// ======================= generic bf16 GEMM ==================================
__global__ __launch_bounds__(256, 2) void gemm_bf(
    const __nv_bfloat16* __restrict__ A, int lda,
    const __nv_bfloat16* __restrict__ W, int K,
    const float* __restrict__ bias,
    float* __restrict__ C, int ldc,
    __nv_bfloat16* __restrict__ Cbf, int ldcb)
{
    const int KB = K >> 5;
    GEMM_PROLOGUE(A, lda, W, K)
#pragma unroll
    for (int mt = 0; mt < 2; ++mt) {
#pragma unroll
        for (int nt = 0; nt < 8; ++nt) {
            int row = m0 + (wm << 5) + (mt << 4) + (lane >> 2);
            int col = n0 + (wn << 6) + (nt << 3) + ((lane & 3) << 1);
            float2 bv = *(const float2*)&bias[col];
            float2 o0 = {acc[mt][nt][0] + bv.x, acc[mt][nt][1] + bv.y};
            float2 o1 = {acc[mt][nt][2] + bv.x, acc[mt][nt][3] + bv.y};
            if (C) {
                *(float2*)&C[(size_t)row * ldc + col] = o0;
                *(float2*)&C[(size_t)(row + 8) * ldc + col] = o1;
            }
            if (Cbf) {
                __nv_bfloat162 p0 = {__float2bfloat16_rn(o0.x), __float2bfloat16_rn(o0.y)};
                __nv_bfloat162 p1 = {__float2bfloat16_rn(o1.x), __float2bfloat16_rn(o1.y)};
                *(__nv_bfloat162*)&Cbf[(size_t)row * ldcb + col] = p0;
                *(__nv_bfloat162*)&Cbf[(size_t)(row + 8) * ldcb + col] = p1;
            }
        }
    }
}

// ================= h_n GEMM with fused GRU update ===========================
// acc = h @ Whh_n^T; epilogue: n = tanh(i_n + r*(h_n+b_hh_n)); h' = (1-z)n+z h.
__global__ __launch_bounds__(256, 2) void gemm_hn_gru(
    const __nv_bfloat16* __restrict__ A,    // h bf16 (ld 768)
    const __nv_bfloat16* __restrict__ W,    // Whh_n [512,512]
    const float* __restrict__ bias,         // b_hh_n
    const float* __restrict__ grz,          // [B,1024] r|z (biased)
    const float* __restrict__ inb,          // [B,512] i_n (+b_ih_n)
    const float* __restrict__ hin,          // [B,512] fp32
    float* __restrict__ hout,
    __nv_bfloat16* __restrict__ habf)       // Anxt base; h at +256, ld 768
{
    const int KB = 16;
    GEMM_PROLOGUE(A, 768, W, 512)
    CP_WAIT0;

    float* st = (float*)smem;               // [64][132] staging
#pragma unroll 1
    for (int half = 0; half < 2; ++half) {
        __syncthreads();
        if ((wm >> 1) == half) {
            int rl0 = ((wm & 1) << 5);
#pragma unroll
            for (int mt = 0; mt < 2; ++mt) {
#pragma unroll
                for (int nt = 0; nt < 8; ++nt) {
                    int col = (wn << 6) + (nt << 3) + ((lane & 3) << 1);
                    float2 bv = *(const float2*)&bias[n0 + col];
                    int rl = rl0 + (mt << 4) + (lane >> 2);
                    st[rl * 132 + col]       = acc[mt][nt][0] + bv.x;
                    st[rl * 132 + col + 1]   = acc[mt][nt][1] + bv.y;
                    st[(rl + 8) * 132 + col]     = acc[mt][nt][2] + bv.x;
                    st[(rl + 8) * 132 + col + 1] = acc[mt][nt][3] + bv.y;
                }
            }
        }
        __syncthreads();
#pragma unroll
        for (int t = 0; t < 8; ++t) {
            int idx = tid + (t << 8);
            int r = idx >> 5, q = idx & 31;
            int rg = m0 + (half << 6) + r;
            int j = n0 + (q << 2);
            float4 hn = *(float4*)&st[r * 132 + (q << 2)];
            float4 rr = *(const float4*)&grz[(size_t)rg * 1024 + j];
            float4 zz = *(const float4*)&grz[(size_t)rg * 1024 + 512 + j];
            float4 ii = *(const float4*)&inb[(size_t)rg * 512 + j];
            float4 hh = *(const float4*)&hin[(size_t)rg * 512 + j];
            float4 o;
            { float rs = sigm(rr.x), zs = sigm(zz.x);
              o.x = (1.f - zs) * tanhf(ii.x + rs * hn.x) + zs * hh.x; }
            { float rs = sigm(rr.y), zs = sigm(zz.y);
              o.y = (1.f - zs) * tanhf(ii.y + rs * hn.y) + zs * hh.y; }
            { float rs = sigm(rr.z), zs = sigm(zz.z);
              o.z = (1.f - zs) * tanhf(ii.z + rs * hn.z) + zs * hh.z; }
            { float rs = sigm(rr.w), zs = sigm(zz.w);
              o.w = (1.f - zs) * tanhf(ii.w + rs * hn.w) + zs * hh.w; }
            *(float4*)&hout[(size_t)rg * 512 + j] = o;
            __nv_bfloat162 p0 = {__float2bfloat16_rn(o.x), __float2bfloat16_rn(o.y)};
            __nv_bfloat162 p1 = {__float2bfloat16_rn(o.z), __float2bfloat16_rn(o.w)};
            __nv_bfloat162* dst = (__nv_bfloat162*)(habf + (size_t)rg * 768 + 256 + j);
            dst[0] = p0; dst[1] = p1;
        }
    }
}

// ============ fused logits GEMM + gumbel softmax + entropy + emb GEMM =======
// Block: 256 thr, 32 batch rows; grid 128.  Dyn smem 160KB:
//   [0,32K)    A slabs (h bf16, then sample bf16), 16 x 2KB swizzled
//   [32K,160K) 4 x 32KB weight stages (Wo) / logits fp32 scratch / We stages
__global__ __launch_bounds__(256, 1) void logsoftemb(
    const __nv_bfloat16* __restrict__ Hb,   // h bf16 (ld 768)
    const __nv_bfloat16* __restrict__ Wo,   // [512,512]
    const float* __restrict__ bo,
    const float* __restrict__ u,            // noise slab [B,512]
    const __nv_bfloat16* __restrict__ We,   // [256,512]
    const float* __restrict__ be,
    float* __restrict__ seq, float* __restrict__ ent,
    __nv_bfloat16* __restrict__ Ebf,        // Anxt base (e-slot), ld 768
    int l)
{
    extern __shared__ __align__(1024) char dsm[];
    const int tid = threadIdx.x, wn = tid >> 5, lane = tid & 31;
    const int b0 = blockIdx.x << 5;
    const uint32_t sA = (uint32_t)__cvta_generic_to_shared(dsm);
    const uint32_t sStg = sA + 32768u;
    float* slog = (float*)(dsm + 32768);    // [32][512] fp32

    // ---- issue A tile (h, 32 rows x 512 cols -> 16 swizzled slabs) ----
#pragma unroll
    for (int t = 0; t < 8; ++t) {
        int i = tid + (t << 8);             // 0..2047
        int s = i >> 7, r = (i >> 2) & 31, c = i & 3;
        cp16(sA + (s << 11) + SWZ(r, c),
             Hb + (size_t)(b0 + r) * 768 + (s << 5) + (c << 3));
    }
    CP_COMMIT;

    auto issueWo = [&](int s, int stg) {
        uint32_t sb = sStg + ((uint32_t)stg << 15);
#pragma unroll
        for (int t = 0; t < 8; ++t) {
            int i = tid + (t << 8);         // 0..2047
            int rr = i >> 2, c = i & 3;
            cp16(sb + SWZ(rr, c), Wo + (size_t)rr * 512 + (s << 5) + (c << 3));
        }
    };
    const int arow0 = (lane & 7) + (((lane >> 3) & 1) << 3);
    const int acb = (lane >> 4) & 1;
    const int bcb = (lane >> 3) & 1;

    float acc[2][8][4];
#pragma unroll
    for (int a_ = 0; a_ < 2; a_++)
#pragma unroll
        for (int b_ = 0; b_ < 8; b_++)
#pragma unroll
            for (int c_ = 0; c_ < 4; c_++) acc[a_][b_][c_] = 0.f;

    issueWo(0, 0); CP_COMMIT;
    issueWo(1, 1); CP_COMMIT;
    issueWo(2, 2); CP_COMMIT;
#pragma unroll 1
    for (int s = 0; s < 16; ++s) {
        CP_WAIT2;
        __syncthreads();
        if (s + 3 < 16) issueWo(s + 3, (s + 3) & 3);
        CP_COMMIT;
        uint32_t bb = sStg + ((uint32_t)(s & 3) << 15);
        uint32_t ab = sA + ((uint32_t)s << 11);
#pragma unroll
        for (int ks = 0; ks < 2; ++ks) {
            uint32_t afr[2][4];
#pragma unroll
            for (int mt = 0; mt < 2; ++mt) {
                int row = arow0 + (mt << 4);
                LDM_X4(afr[mt], ab + SWZ(row, (ks << 1) + acb));
            }
            uint32_t bfr[8][2];
#pragma unroll
            for (int p = 0; p < 4; ++p) {
                int row = (wn << 6) + arow0 - (((lane >> 3) & 1) << 3)
                          + (((lane >> 4) & 1) << 3) + (p << 4);
                uint32_t t4[4];
                LDM_X4(t4, bb + SWZ(row, (ks << 1) + bcb));
                bfr[2 * p][0] = t4[0]; bfr[2 * p][1] = t4[1];
                bfr[2 * p + 1][0] = t4[2]; bfr[2 * p + 1][1] = t4[3];
            }
#pragma unroll
            for (int nt = 0; nt < 8; ++nt) {
                MMA_BF16(acc[0][nt], afr[0], bfr[nt]);
                MMA_BF16(acc[1][nt], afr[1], bfr[nt]);
            }
        }
    }
    CP_WAIT0;
    __syncthreads();

    // ---- logits + bias -> slog ----
#pragma unroll
    for (int mt = 0; mt < 2; ++mt) {
#pragma unroll
        for (int nt = 0; nt < 8; ++nt) {
            int col = (wn << 6) + (nt << 3) + ((lane & 3) << 1);
            int row = (lane >> 2) + (mt << 4);
            float2 bv = *(const float2*)&bo[col];
            slog[row * 512 + col]     = acc[mt][nt][0] + bv.x;
            slog[row * 512 + col + 1] = acc[mt][nt][1] + bv.y;
            slog[(row + 8) * 512 + col]     = acc[mt][nt][2] + bv.x;
            slog[(row + 8) * 512 + col + 1] = acc[mt][nt][3] + bv.y;
        }
    }
    __syncthreads();

    // ---- gumbel softmax + entropy; bf16 sample back into A slabs ----
    __nv_bfloat16* sAp = (__nv_bfloat16*)dsm;
#pragma unroll 1
    for (int rr = 0; rr < 4; ++rr) {
        int row = (wn << 2) + rr;
        int gb = b0 + row;
        float v[16];
        float m = -INFINITY;
#pragma unroll
        for (int i = 0; i < 16; ++i) {
            float uu = u[(size_t)gb * 512 + lane + 32 * i];
            float g = -logf(-logf(uu));
            v[i] = slog[row * 512 + lane + 32 * i] + g;
            m = fmaxf(m, v[i]);
        }
#pragma unroll
        for (int o = 16; o; o >>= 1) m = fmaxf(m, __shfl_xor_sync(0xffffffffu, m, o));
        float sum = 0.f;
#pragma unroll
        for (int i = 0; i < 16; ++i) { v[i] = expf(v[i] - m); sum += v[i]; }
#pragma unroll
        for (int o = 16; o; o >>= 1) sum += __shfl_xor_sync(0xffffffffu, sum, o);
        float inv = 1.f / sum;
        float eacc = 0.f;
        float* srow = seq + ((size_t)gb * Ldim + l) * 512;
#pragma unroll
        for (int i = 0; i < 16; ++i) {
            float p = v[i] * inv;
            srow[lane + 32 * i] = p;
            // sample bf16 into A-slab layout: slab i, row, chunk lane>>3, elem lane&7
            uint32_t off = (uint32_t)(i << 11) + SWZ(row, lane >> 3) + ((lane & 7) << 1);
            *(__nv_bfloat16*)((char*)sAp + off) = __float2bfloat16_rn(p);
            float t = fmaxf(log2f(p), MIN_REAL);
            eacc -= p * t;
        }
#pragma unroll
        for (int o = 16; o; o >>= 1) eacc += __shfl_xor_sync(0xffffffffu, eacc, o);
        if (lane == 0) ent[(size_t)gb * Ldim + l] = eacc;
    }
    __syncthreads();

    // ---- emb GEMM: e = sample @ We^T + be  (N=256: warp covers 32 cols) ----
    auto issueWe = [&](int s, int stg) {
        uint32_t sb = sStg + ((uint32_t)stg << 14);
#pragma unroll
        for (int t = 0; t < 4; ++t) {
            int i = tid + (t << 8);         // 0..1023
            int rr = i >> 2, c = i & 3;
            cp16(sb + SWZ(rr, c), We + (size_t)rr * 512 + (s << 5) + (c << 3));
        }
    };
    float acc2[2][4][4];
#pragma unroll
    for (int a_ = 0; a_ < 2; a_++)
#pragma unroll
        for (int b_ = 0; b_ < 4; b_++)
#pragma unroll
            for (int c_ = 0; c_ < 4; c_++) acc2[a_][b_][c_] = 0.f;

    issueWe(0, 0); CP_COMMIT;
    issueWe(1, 1); CP_COMMIT;
    issueWe(2, 2); CP_COMMIT;
#pragma unroll 1
    for (int s = 0; s < 16; ++s) {
        CP_WAIT2;
        __syncthreads();
        if (s + 3 < 16) issueWe(s + 3, (s + 3) & 3);
        CP_COMMIT;
        uint32_t bb = sStg + ((uint32_t)(s & 3) << 14);
        uint32_t ab = sA + ((uint32_t)s << 11);
#pragma unroll
        for (int ks = 0; ks < 2; ++ks) {
            uint32_t afr[2][4];
#pragma unroll
            for (int mt = 0; mt < 2; ++mt) {
                int row = arow0 + (mt << 4);
                LDM_X4(afr[mt], ab + SWZ(row, (ks << 1) + acb));
            }
            uint32_t bfr[4][2];
#pragma unroll
            for (int p = 0; p < 2; ++p) {
                int row = (wn << 5) + (lane & 7) + (((lane >> 4) & 1) << 3) + (p << 4);
                uint32_t t4[4];
                LDM_X4(t4, bb + SWZ(row, (ks << 1) + bcb));
                bfr[2 * p][0] = t4[0]; bfr[2 * p][1] = t4[1];
                bfr[2 * p + 1][0] = t4[2]; bfr[2 * p + 1][1] = t4[3];
            }
#pragma unroll
            for (int nt = 0; nt < 4; ++nt) {
                MMA_BF16(acc2[0][nt], afr[0], bfr[nt]);
                MMA_BF16(acc2[1][nt], afr[1], bfr[nt]);
            }
        }
    }
    // epilogue: bias + bf16 -> Anxt e-slot
#pragma unroll
    for (int mt = 0; mt < 2; ++mt) {
#pragma unroll
        for (int nt = 0; nt < 4; ++nt) {
            int col = (wn << 5) + (nt << 3) + ((lane & 3) << 1);
            int row = b0 + (lane >> 2) + (mt << 4);
            float2 bv = *(const float2*)&be[col];
            __nv_bfloat162 p0 = {__float2bfloat16_rn(acc2[mt][nt][0] + bv.x),
                                 __float2bfloat16_rn(acc2[mt][nt][1] + bv.y)};
            __nv_bfloat162 p1 = {__float2bfloat16_rn(acc2[mt][nt][2] + bv.x),
                                 __float2bfloat16_rn(acc2[mt][nt][3] + bv.y)};
            *(__nv_bfloat162*)&Ebf[(size_t)row * 768 + col] = p0;
            *(__nv_bfloat162*)&Ebf[(size_t)(row + 8) * 768 + col] = p1;
        }
    }
}

// ======================= host launcher ======================================
extern "C" void kernel_launch(void* const* d_in, const int* in_sizes, int n_in,
                              void* d_out, int out_size)
{
    const float* x       = (const float*)d_in[0];
    const float* noise   = (const float*)d_in[1];
    const float* W_agent = (const float*)d_in[2];
    const float* b_agent = (const float*)d_in[3];
    const float* W_ih    = (const float*)d_in[4];
    const float* W_hh    = (const float*)d_in[5];
    const float* b_ih    = (const float*)d_in[6];
    const float* b_hh    = (const float*)d_in[7];
    const float* W_out   = (const float*)d_in[8];
    const float* b_out   = (const float*)d_in[9];
    const float* W_emb   = (const float*)d_in[10];
    const float* b_emb   = (const float*)d_in[11];
    const float* sos     = (const float*)d_in[12];

    float* out = (float*)d_out;
    float* ent = out + (size_t)Bdim * Ldim * Vdim;

    float *hbuf0, *grz, *inb, *brz;
    __nv_bfloat16 *abf0, *xbf, *wrz, *wihn, *whhn, *wo, *we, *wa;
    cudaGetSymbolAddress((void**)&hbuf0, g_h);
    float* hbuf1 = hbuf0 + (size_t)Bdim * Hdim;
    cudaGetSymbolAddress((void**)&abf0, g_abf);
    __nv_bfloat16* abf1 = abf0 + (size_t)Bdim * 768;
    cudaGetSymbolAddress((void**)&grz, g_grz);
    cudaGetSymbolAddress((void**)&inb, g_in);
    cudaGetSymbolAddress((void**)&xbf, g_xbf);
    cudaGetSymbolAddress((void**)&wrz, g_wrz);
    cudaGetSymbolAddress((void**)&wihn, g_wihn);
    cudaGetSymbolAddress((void**)&whhn, g_whhn);
    cudaGetSymbolAddress((void**)&wo, g_wo);
    cudaGetSymbolAddress((void**)&we, g_we);
    cudaGetSymbolAddress((void**)&wa, g_wa);
    cudaGetSymbolAddress((void**)&brz, g_brz);

    const int LS_SMEM = 163840;
    cudaFuncSetAttribute(logsoftemb, cudaFuncAttributeMaxDynamicSharedMemorySize, LS_SMEM);

    // ---- one-time prep ----
    build_wrz_kernel<<<(1024 * 768) / 256, 256>>>(W_ih, W_hh);
    build_brz_kernel<<<4, 256>>>(b_ih, b_hh);
    cvt_kernel<<<(512 * 256) / 256, 256>>>(wihn, W_ih + 1024 * 256, 512 * 256);
    cvt_kernel<<<(512 * 512) / 256, 256>>>(whhn, W_hh + 1024 * 512, 512 * 512);
    cvt_kernel<<<(512 * 512) / 256, 256>>>(wo, W_out, 512 * 512);
    cvt_kernel<<<(256 * 512) / 256, 256>>>(we, W_emb, 256 * 512);
    cvt_kernel<<<(512 * 512) / 256, 256>>>(wa, W_agent, 512 * 512);
    cvt_kernel<<<(Bdim * DIN) / 256, 256>>>(xbf, x, Bdim * DIN);
    init_e0_kernel<<<(Bdim * Edim) / 256, 256>>>(sos);

    // h0 = x @ W_agent^T + b_agent  (fp32 master + bf16 into A'[0] h-slot)
    gemm_bf<<<dim3(4, 32), 256>>>(xbf, DIN, wa, DIN, b_agent,
                                  hbuf0, Hdim, abf0 + 256, 768);

    for (int l = 0; l < Ldim; l++) {
        __nv_bfloat16* Ain  = (l & 1) ? abf1 : abf0;
        __nv_bfloat16* Anxt = (l & 1) ? abf0 : abf1;
        float* hin  = (l & 1) ? hbuf1 : hbuf0;
        float* hout = (l & 1) ? hbuf0 : hbuf1;

        // r,z (summed): [e|h] @ Wrz^T + (b_ih+b_hh)    K=768
        gemm_bf<<<dim3(8, 32), 256>>>(Ain, 768, wrz, 768, brz,
                                      grz, 1024, (__nv_bfloat16*)0, 0);
        // i_n = e @ Wih_n^T + b_ih_n                   K=256
        gemm_bf<<<dim3(4, 32), 256>>>(Ain, 768, wihn, 256, b_ih + 1024,
                                      inb, 512, (__nv_bfloat16*)0, 0);
        // h_n GEMM + fused GRU update -> hout, Anxt h-slot
        gemm_hn_gru<<<dim3(4, 32), 256>>>(Ain + 256, whhn, b_hh + 1024,
                                          grz, inb, hin, hout, Anxt);
        // logits + gumbel softmax + entropy + emb -> out, ent, Anxt e-slot
        logsoftemb<<<Bdim / 32, 256, LS_SMEM>>>(
            Anxt + 256, wo, b_out, noise + (size_t)l * Bdim * Vdim,
            we, b_emb, out, ent, Anxt, l);
    }
    (void)in_sizes; (void)n_in; (void)out_size;
}

// round 8
// speedup vs baseline: 1.0681x; 1.0360x over previous
#include <cuda_runtime.h>
#include <cuda_bf16.h>
#include <math.h>
#include <stdint.h>

#define Bdim 4096
#define DIN  512
#define Hdim 512
#define Edim 256
#define Vdim 512
#define Ldim 32
#define MIN_REAL (-3.4028234663852886e38f)

// ---------------- scratch (device globals; no allocation allowed) ----------
__device__ float         g_h[2][(size_t)Bdim * Hdim];      // fp32 hidden (master)
__device__ __nv_bfloat16 g_abf[2][(size_t)Bdim * 768];     // [e | h] bf16, ping-pong
__device__ float         g_grz[(size_t)Bdim * 1024];       // summed r,z pre-activations
__device__ float         g_in[(size_t)Bdim * Hdim];        // i_n (+b_ih_n)
__device__ float         g_hn[(size_t)Bdim * Hdim];        // h_n (+b_hh_n)
__device__ float         g_logits[(size_t)Bdim * Vdim];
__device__ __nv_bfloat16 g_sbf[(size_t)Bdim * Vdim];       // bf16 sample
__device__ __nv_bfloat16 g_xbf[(size_t)Bdim * DIN];
__device__ __nv_bfloat16 g_wrz[1024 * 768];                // [Wih_rz | Whh_rz]
__device__ __nv_bfloat16 g_wihn[512 * 256];
__device__ __nv_bfloat16 g_whhn[512 * 512];
__device__ __nv_bfloat16 g_wo[512 * 512];
__device__ __nv_bfloat16 g_we[256 * 512];
__device__ __nv_bfloat16 g_wa[512 * 512];
__device__ float         g_brz[1024];

__device__ __forceinline__ float sigm(float x) { return 1.f / (1.f + expf(-x)); }

#define MMA_BF16(d, a, b) \
    asm volatile("mma.sync.aligned.m16n8k16.row.col.f32.bf16.bf16.f32 " \
        "{%0,%1,%2,%3}, {%4,%5,%6,%7}, {%8,%9}, {%0,%1,%2,%3};" \
        : "+f"((d)[0]), "+f"((d)[1]), "+f"((d)[2]), "+f"((d)[3]) \
        : "r"((a)[0]), "r"((a)[1]), "r"((a)[2]), "r"((a)[3]), \
          "r"((b)[0]), "r"((b)[1]))

#define LDM_X4(d, addr) \
    asm volatile("ldmatrix.sync.aligned.m8n8.x4.shared.b16 {%0,%1,%2,%3}, [%4];" \
        : "=r"((d)[0]), "=r"((d)[1]), "=r"((d)[2]), "=r"((d)[3]) : "r"(addr))

__device__ __forceinline__ void cp16(uint32_t dst, const void* src) {
    asm volatile("cp.async.cg.shared.global [%0], [%1], 16;" :: "r"(dst), "l"(src) : "memory");
}
#define CP_COMMIT  asm volatile("cp.async.commit_group;" ::: "memory")
#define CP_WAIT2   asm volatile("cp.async.wait_group 2;" ::: "memory")

// swizzled byte offset for (row, 8-elem chunk) in a 32-col bf16 k-slab tile
#define SWZ(r, c) ((uint32_t)((((r) << 2) + ((c) ^ (((r) >> 1) & 3))) << 4))

// ---------------- prep kernels ----------------------------------------------
__global__ void cvt_kernel(__nv_bfloat16* __restrict__ dst,
                           const float* __restrict__ src, int n) {
    int i = blockIdx.x * blockDim.x + threadIdx.x;
    if (i < n) dst[i] = __float2bfloat16_rn(src[i]);
}
__global__ void build_wrz_kernel(const float* __restrict__ Wih,
                                 const float* __restrict__ Whh) {
    int i = blockIdx.x * blockDim.x + threadIdx.x;   // 1024*768
    int g = i / 768, c = i % 768;
    float v = (c < 256) ? Wih[g * 256 + c] : Whh[g * 512 + (c - 256)];
    g_wrz[i] = __float2bfloat16_rn(v);
}
__global__ void build_brz_kernel(const float* __restrict__ bih,
                                 const float* __restrict__ bhh) {
    int i = blockIdx.x * blockDim.x + threadIdx.x;   // 1024
    g_brz[i] = bih[i] + bhh[i];
}
__global__ void init_e0_kernel(const float* __restrict__ sos) {
    int i = blockIdx.x * blockDim.x + threadIdx.x;   // B*256
    int b = i >> 8, c = i & 255;
    g_abf[0][(size_t)b * 768 + c] = __float2bfloat16_rn(sos[c]);
}

// ======================= bf16 tensor-core GEMM ==============================
// C[M,N] = A[M,K] @ W[N,K]^T + bias.  Block 128x128, 128 thr (4 warps),
// warp tile 64x64 (4 m-frags x 8 n-frags), K-block 32, 4-stage cp.async,
// ldmatrix.x4 fragment loads from XOR-swizzled SMEM.
__global__ __launch_bounds__(128, 2) void gemm_bf(
    const __nv_bfloat16* __restrict__ A, int lda,
    const __nv_bfloat16* __restrict__ W, int K,
    const float* __restrict__ bias,
    float* __restrict__ C, int ldc,
    __nv_bfloat16* __restrict__ Cbf, int ldcb)
{
    __shared__ __align__(1024) char smem[4 * 16384];   // stage: A 8K | B 8K
    const int tid = threadIdx.x, wid = tid >> 5, lane = tid & 31;
    const int wm = wid & 1, wn = wid >> 1;
    const int m0 = blockIdx.y << 7, n0 = blockIdx.x << 7;
    const int KB = K >> 5;
    const uint32_t smbase = (uint32_t)__cvta_generic_to_shared(smem);

    float acc[4][8][4];
#pragma unroll
    for (int a_ = 0; a_ < 4; a_++)
#pragma unroll
        for (int b_ = 0; b_ < 8; b_++)
#pragma unroll
            for (int c_ = 0; c_ < 4; c_++) acc[a_][b_][c_] = 0.f;

    const int cr = tid >> 2, cc = tid & 3;          // cp.async chunk geometry
    auto issue = [&](int kb, int s) {
        uint32_t sb = smbase + ((uint32_t)s << 14);
#pragma unroll
        for (int it = 0; it < 4; ++it) {
            int rr = cr + (it << 5);
            uint32_t off = SWZ(rr, cc);
            cp16(sb + off,        A + (size_t)(m0 + rr) * lda + (kb << 5) + (cc << 3));
            cp16(sb + 8192 + off, W + (size_t)(n0 + rr) * K   + (kb << 5) + (cc << 3));
        }
    };

    const int arow0 = (wm << 6) + (lane & 7) + (((lane >> 3) & 1) << 3);
    const int acb   = (lane >> 4) & 1;
    const int nrow0 = (wn << 6) + (lane & 7) + (((lane >> 4) & 1) << 3);
    const int bcb   = (lane >> 3) & 1;

    auto compute = [&](int s) {
        uint32_t ab = smbase + ((uint32_t)s << 14);
        uint32_t bb = ab + 8192;
#pragma unroll
        for (int ks = 0; ks < 2; ++ks) {
            uint32_t afr[4][4];
#pragma unroll
            for (int mt = 0; mt < 4; ++mt)
                LDM_X4(afr[mt], ab + SWZ(arow0 + (mt << 4), (ks << 1) + acb));
            uint32_t bfr[8][2];
#pragma unroll
            for (int p = 0; p < 4; ++p) {
                uint32_t t4[4];
                LDM_X4(t4, bb + SWZ(nrow0 + (p << 4), (ks << 1) + bcb));
                bfr[2 * p][0] = t4[0]; bfr[2 * p][1] = t4[1];
                bfr[2 * p + 1][0] = t4[2]; bfr[2 * p + 1][1] = t4[3];
            }
#pragma unroll
            for (int mt = 0; mt < 4; ++mt)
#pragma unroll
                for (int nt = 0; nt < 8; ++nt)
                    MMA_BF16(acc[mt][nt], afr[mt], bfr[nt]);
        }
    };

    issue(0, 0); CP_COMMIT;
    issue(1, 1); CP_COMMIT;
    issue(2, 2); CP_COMMIT;
#pragma unroll 1
    for (int kb = 0; kb < KB; ++kb) {
        CP_WAIT2;
        __syncthreads();
        if (kb + 3 < KB) issue(kb + 3, (kb + 3) & 3);
        CP_COMMIT;
        compute(kb & 3);
    }

    // epilogue: bias + stores
#pragma unroll
    for (int mt = 0; mt < 4; ++mt) {
#pragma unroll
        for (int nt = 0; nt < 8; ++nt) {
            int row = m0 + (wm << 6) + (mt << 4) + (lane >> 2);
            int col = n0 + (wn << 6) + (nt << 3) + ((lane & 3) << 1);
            float2 bv = *(const float2*)&bias[col];
            float2 o0 = {acc[mt][nt][0] + bv.x, acc[mt][nt][1] + bv.y};
            float2 o1 = {acc[mt][nt][2] + bv.x, acc[mt][nt][3] + bv.y};
            if (C) {
                *(float2*)&C[(size_t)row * ldc + col] = o0;
                *(float2*)&C[(size_t)(row + 8) * ldc + col] = o1;
            }
            if (Cbf) {
                __nv_bfloat162 p0 = {__float2bfloat16_rn(o0.x), __float2bfloat16_rn(o0.y)};
                __nv_bfloat162 p1 = {__float2bfloat16_rn(o1.x), __float2bfloat16_rn(o1.y)};
                *(__nv_bfloat162*)&Cbf[(size_t)row * ldcb + col] = p0;
                *(__nv_bfloat162*)&Cbf[(size_t)(row + 8) * ldcb + col] = p1;
            }
        }
    }
}

// ======================= elementwise GRU update =============================
__global__ __launch_bounds__(256) void gru_ew(
    const float4* __restrict__ Grz, const float4* __restrict__ In,
    const float4* __restrict__ Hn, const float4* __restrict__ hin,
    float4* __restrict__ hout, __nv_bfloat16* __restrict__ habf)
{
    int i = blockIdx.x * blockDim.x + threadIdx.x;   // B * 128
    int b = i >> 7, jq = i & 127;
    float4 gr = Grz[(size_t)b * 256 + jq];
    float4 gz = Grz[(size_t)b * 256 + 128 + jq];
    float4 gi = In[(size_t)b * 128 + jq];
    float4 gh = Hn[(size_t)b * 128 + jq];
    float4 h = hin[(size_t)b * 128 + jq];
    float4 o;
    { float r = sigm(gr.x), z = sigm(gz.x);
      o.x = (1.f - z) * tanhf(gi.x + r * gh.x) + z * h.x; }
    { float r = sigm(gr.y), z = sigm(gz.y);
      o.y = (1.f - z) * tanhf(gi.y + r * gh.y) + z * h.y; }
    { float r = sigm(gr.z), z = sigm(gz.z);
      o.z = (1.f - z) * tanhf(gi.z + r * gh.z) + z * h.z; }
    { float r = sigm(gr.w), z = sigm(gz.w);
      o.w = (1.f - z) * tanhf(gi.w + r * gh.w) + z * h.w; }
    hout[(size_t)b * 128 + jq] = o;
    __nv_bfloat162 p0 = {__float2bfloat16_rn(o.x), __float2bfloat16_rn(o.y)};
    __nv_bfloat162 p1 = {__float2bfloat16_rn(o.z), __float2bfloat16_rn(o.w)};
    __nv_bfloat162* dst = (__nv_bfloat162*)(habf + (size_t)b * 768 + 256 + (jq << 2));
    dst[0] = p0; dst[1] = p1;
}

// ======================= gumbel softmax + entropy ===========================
__global__ __launch_bounds__(256) void softmax_kernel(
    const float* __restrict__ logits, const float* __restrict__ u,
    float* __restrict__ seq, float* __restrict__ ent,
    __nv_bfloat16* __restrict__ sbf, int l)
{
    const int warp = threadIdx.x >> 5, lane = threadIdx.x & 31;
    const int b = blockIdx.x * 8 + warp;
    const float* lrow = logits + (size_t)b * Vdim;
    const float* urow = u + (size_t)b * Vdim;

    float s[16];
    float m = -INFINITY;
#pragma unroll
    for (int i = 0; i < 16; i++) {
        float uu = urow[lane + 32 * i];
        float g = -logf(-logf(uu));
        s[i] = lrow[lane + 32 * i] + g;
        m = fmaxf(m, s[i]);
    }
#pragma unroll
    for (int o = 16; o; o >>= 1) m = fmaxf(m, __shfl_xor_sync(0xffffffffu, m, o));
    float sum = 0.f;
#pragma unroll
    for (int i = 0; i < 16; i++) { s[i] = expf(s[i] - m); sum += s[i]; }
#pragma unroll
    for (int o = 16; o; o >>= 1) sum += __shfl_xor_sync(0xffffffffu, sum, o);

    float inv = 1.f / sum;
    float eacc = 0.f;
    float* srow = seq + ((size_t)b * Ldim + l) * Vdim;
    __nv_bfloat16* brow = sbf + (size_t)b * Vdim;
#pragma unroll
    for (int i = 0; i < 16; i++) {
        float p = s[i] * inv;
        srow[lane + 32 * i] = p;
        brow[lane + 32 * i] = __float2bfloat16_rn(p);
        float t = fmaxf(log2f(p), MIN_REAL);
        eacc -= p * t;
    }
#pragma unroll
    for (int o = 16; o; o >>= 1) eacc += __shfl_xor_sync(0xffffffffu, eacc, o);
    if (lane == 0) ent[(size_t)b * Ldim + l] = eacc;
}

// ======================= host launcher ======================================
extern "C" void kernel_launch(void* const* d_in, const int* in_sizes, int n_in,
                              void* d_out, int out_size)
{
    const float* x       = (const float*)d_in[0];
    const float* noise   = (const float*)d_in[1];
    const float* W_agent = (const float*)d_in[2];
    const float* b_agent = (const float*)d_in[3];
    const float* W_ih    = (const float*)d_in[4];
    const float* W_hh    = (const float*)d_in[5];
    const float* b_ih    = (const float*)d_in[6];
    const float* b_hh    = (const float*)d_in[7];
    const float* W_out   = (const float*)d_in[8];
    const float* b_out   = (const float*)d_in[9];
    const float* W_emb   = (const float*)d_in[10];
    const float* b_emb   = (const float*)d_in[11];
    const float* sos     = (const float*)d_in[12];

    float* out = (float*)d_out;
    float* ent = out + (size_t)Bdim * Ldim * Vdim;

    float *hbuf0, *grz, *inb, *hnb, *lbuf, *brz;
    __nv_bfloat16 *abf0, *sbf, *xbf, *wrz, *wihn, *whhn, *wo, *we, *wa;
    cudaGetSymbolAddress((void**)&hbuf0, g_h);
    float* hbuf1 = hbuf0 + (size_t)Bdim * Hdim;
    cudaGetSymbolAddress((void**)&abf0, g_abf);
    __nv_bfloat16* abf1 = abf0 + (size_t)Bdim * 768;
    cudaGetSymbolAddress((void**)&grz, g_grz);
    cudaGetSymbolAddress((void**)&inb, g_in);
    cudaGetSymbolAddress((void**)&hnb, g_hn);
    cudaGetSymbolAddress((void**)&lbuf, g_logits);
    cudaGetSymbolAddress((void**)&sbf, g_sbf);
    cudaGetSymbolAddress((void**)&xbf, g_xbf);
    cudaGetSymbolAddress((void**)&wrz, g_wrz);
    cudaGetSymbolAddress((void**)&wihn, g_wihn);
    cudaGetSymbolAddress((void**)&whhn, g_whhn);
    cudaGetSymbolAddress((void**)&wo, g_wo);
    cudaGetSymbolAddress((void**)&we, g_we);
    cudaGetSymbolAddress((void**)&wa, g_wa);
    cudaGetSymbolAddress((void**)&brz, g_brz);

    // ---- one-time prep ----
    build_wrz_kernel<<<(1024 * 768) / 256, 256>>>(W_ih, W_hh);
    build_brz_kernel<<<4, 256>>>(b_ih, b_hh);
    cvt_kernel<<<(512 * 256) / 256, 256>>>(wihn, W_ih + 1024 * 256, 512 * 256);
    cvt_kernel<<<(512 * 512) / 256, 256>>>(whhn, W_hh + 1024 * 512, 512 * 512);
    cvt_kernel<<<(512 * 512) / 256, 256>>>(wo, W_out, 512 * 512);
    cvt_kernel<<<(256 * 512) / 256, 256>>>(we, W_emb, 256 * 512);
    cvt_kernel<<<(512 * 512) / 256, 256>>>(wa, W_agent, 512 * 512);
    cvt_kernel<<<(Bdim * DIN) / 256, 256>>>(xbf, x, Bdim * DIN);
    init_e0_kernel<<<(Bdim * Edim) / 256, 256>>>(sos);

    // h0 = x @ W_agent^T + b_agent  (fp32 master + bf16 into A'[0] h-slot)
    gemm_bf<<<dim3(4, 32), 128>>>(xbf, DIN, wa, DIN, b_agent,
                                  hbuf0, Hdim, abf0 + 256, 768);

    for (int l = 0; l < Ldim; l++) {
        __nv_bfloat16* Ain  = (l & 1) ? abf1 : abf0;
        __nv_bfloat16* Anxt = (l & 1) ? abf0 : abf1;
        float* hin  = (l & 1) ? hbuf1 : hbuf0;
        float* hout = (l & 1) ? hbuf0 : hbuf1;

        // r,z (summed) : [e|h] @ Wrz^T + (b_ih+b_hh)   K=768
        gemm_bf<<<dim3(8, 32), 128>>>(Ain, 768, wrz, 768, brz,
                                      grz, 1024, (__nv_bfloat16*)0, 0);
        // i_n = e @ Wih_n^T + b_ih_n                    K=256
        gemm_bf<<<dim3(4, 32), 128>>>(Ain, 768, wihn, 256, b_ih + 1024,
                                      inb, 512, (__nv_bfloat16*)0, 0);
        // h_n = h @ Whh_n^T + b_hh_n                    K=512
        gemm_bf<<<dim3(4, 32), 128>>>(Ain + 256, 768, whhn, 512, b_hh + 1024,
                                      hnb, 512, (__nv_bfloat16*)0, 0);
        // GRU update -> fp32 h + bf16 h into A'[next]
        gru_ew<<<(Bdim * 128) / 256, 256>>>(
            (const float4*)grz, (const float4*)inb, (const float4*)hnb,
            (const float4*)hin, (float4*)hout, Anxt);
        // logits = h_t @ W_out^T + b_out                K=512
        gemm_bf<<<dim3(4, 32), 128>>>(Anxt + 256, 768, wo, 512, b_out,
                                      lbuf, 512, (__nv_bfloat16*)0, 0);
        // sample + entropy (+ bf16 sample)
        softmax_kernel<<<Bdim / 8, 256>>>(
            lbuf, noise + (size_t)l * Bdim * Vdim, out, ent, sbf, l);
        // e_{l+1} = sample @ W_emb^T + b_emb -> bf16 into A'[next] e-slot
        gemm_bf<<<dim3(2, 32), 128>>>(sbf, 512, we, 512, b_emb,
                                      (float*)0, 0, Anxt, 768);
    }
    (void)in_sizes; (void)n_in; (void)out_size;
}